// round 10
// baseline (speedup 1.0000x reference)
#include <cuda_runtime.h>
#include <math.h>

#define NVOX 65536            // 64*64*16 voxels
#define CCH 64
#define NHEAD 8
#define DHEAD 8

typedef unsigned long long u64;

// ---------------- scratch (device globals; no allocation allowed) ----------
__device__ float f_xu[CCH * NVOX];   // upsampled x, channel-first [c][v]
__device__ float f_q[NVOX * CCH];    // q projection, voxel-major [v][c]
__device__ float f_k[NVOX * CCH];
__device__ float f_v[NVOX * CCH];
__device__ float f_o[CCH * NVOX];    // attention output, channel-first [c][v]
__device__ float g_psum[512], g_psumsq[512];   // [0:256] xu quarters, [256:512] skip quarters
__device__ float g_Wf[3][CCH * CCH];           // folded Wq, Wk, Wv
__device__ float g_bf[3][CCH];

// ---------------- helpers ---------------------------------------------------
__device__ __forceinline__ u64 ffma2(u64 a, u64 b, u64 c) {
    u64 d;
    asm("fma.rn.f32x2 %0, %1, %2, %3;" : "=l"(d) : "l"(a), "l"(b), "l"(c));
    return d;
}
__device__ __forceinline__ u64 fmul2(u64 a, u64 b) {
    u64 d;
    asm("mul.rn.f32x2 %0, %1, %2;" : "=l"(d) : "l"(a), "l"(b));
    return d;
}
__device__ __forceinline__ u64 packdup(float w) {
    unsigned u = __float_as_uint(w);
    return ((u64)u << 32) | (u64)u;
}
__device__ __forceinline__ float f2lo(u64 a) { return __uint_as_float((unsigned)a); }
__device__ __forceinline__ float f2hi(u64 a) { return __uint_as_float((unsigned)(a >> 32)); }

// ---------------- 1) trilinear upsample x(64,32,32,8) -> f_xu(64,64,64,16) --
__global__ __launch_bounds__(256) void upsample_kernel(const float* __restrict__ x) {
    int v = blockIdx.x * 256 + threadIdx.x;
    int h = v >> 10;
    int w = (v >> 4) & 63;
    int z = v & 15;

    const float rh = (float)(31.0 / 63.0);
    const float rw = (float)(31.0 / 63.0);
    const float rz = (float)(7.0 / 15.0);

    float ph = (float)h * rh; int ih = (int)ph; if (ih > 30) ih = 30; float fh = ph - (float)ih;
    float pw = (float)w * rw; int iw = (int)pw; if (iw > 30) iw = 30; float fw = pw - (float)iw;
    float pz = (float)z * rz; int iz = (int)pz; if (iz > 6)  iz = 6;  float fz = pz - (float)iz;

    int base = ih * 256 + iw * 8 + iz;   // strides: h=256, w=8, z=1
    int cbase = blockIdx.y * 8;

#pragma unroll
    for (int ci = 0; ci < 8; ci++) {
        int c = cbase + ci;
        const float* xc = x + c * 8192 + base;
        float c000 = xc[0],   c100 = xc[256], c010 = xc[8],   c110 = xc[264];
        float c001 = xc[1],   c101 = xc[257], c011 = xc[9],   c111 = xc[265];
        float a00 = c000 + fh * (c100 - c000);
        float a10 = c010 + fh * (c110 - c010);
        float a01 = c001 + fh * (c101 - c001);
        float a11 = c011 + fh * (c111 - c011);
        float b0  = a00 + fw * (a10 - a00);
        float b1  = a01 + fw * (a11 - a01);
        f_xu[c * NVOX + v] = b0 + fz * (b1 - b0);
    }
}

// ---------------- 2) per-channel partial sum / sumsq (xu and skip) ----------
__global__ __launch_bounds__(256) void stats_kernel(const float* __restrict__ skip) {
    int b = blockIdx.x;   // 0..511
    const int quart = NVOX / 4;
    const float* p;
    if (b < 256) p = f_xu + (b >> 2) * NVOX + (b & 3) * quart;
    else         p = skip + ((b - 256) >> 2) * NVOX + (b & 3) * quart;

    const float4* p4 = (const float4*)p;
    float s = 0.f, s2 = 0.f;
    for (int i = threadIdx.x; i < quart / 4; i += 256) {
        float4 val = p4[i];
        s  += val.x + val.y + val.z + val.w;
        s2 += val.x * val.x + val.y * val.y + val.z * val.z + val.w * val.w;
    }
    __shared__ float sh1[256], sh2[256];
    sh1[threadIdx.x] = s; sh2[threadIdx.x] = s2;
    __syncthreads();
    for (int off = 128; off > 0; off >>= 1) {
        if (threadIdx.x < off) {
            sh1[threadIdx.x] += sh1[threadIdx.x + off];
            sh2[threadIdx.x] += sh2[threadIdx.x + off];
        }
        __syncthreads();
    }
    if (threadIdx.x == 0) { g_psum[b] = sh1[0]; g_psumsq[b] = sh2[0]; }
}

// ---------------- 3) fold instance-norm (+ q scale) into weights -----------
__global__ void fold_kernel(const float* __restrict__ Wq, const float* __restrict__ bq,
                            const float* __restrict__ Wk, const float* __restrict__ bk,
                            const float* __restrict__ Wv, const float* __restrict__ bv) {
    __shared__ float skv[64], okv[64], sq_[64], oq_[64];
    int t = threadIdx.x;    // 64 threads
    const float invN = 1.0f / 65536.0f;
    float m  = (g_psum[4 * t] + g_psum[4 * t + 1] + g_psum[4 * t + 2] + g_psum[4 * t + 3]) * invN;
    float va = (g_psumsq[4 * t] + g_psumsq[4 * t + 1] + g_psumsq[4 * t + 2] + g_psumsq[4 * t + 3]) * invN - m * m;
    float sc = rsqrtf(va + 1e-5f);
    skv[t] = sc; okv[t] = -m * sc;
    m  = (g_psum[256 + 4 * t] + g_psum[257 + 4 * t] + g_psum[258 + 4 * t] + g_psum[259 + 4 * t]) * invN;
    va = (g_psumsq[256 + 4 * t] + g_psumsq[257 + 4 * t] + g_psumsq[258 + 4 * t] + g_psumsq[259 + 4 * t]) * invN - m * m;
    sc = rsqrtf(va + 1e-5f);
    sq_[t] = sc; oq_[t] = -m * sc;
    __syncthreads();

    const float scale = 0.3535533905932738f;  // dh^-0.5, dh=8
    float aq = 0.f, ak = 0.f, av = 0.f;
    for (int c = 0; c < 64; c++) {
        float wq = Wq[c * 64 + t]; g_Wf[0][c * 64 + t] = wq * sq_[c] * scale; aq += oq_[c] * wq;
        float wk = Wk[c * 64 + t]; g_Wf[1][c * 64 + t] = wk * skv[c];          ak += okv[c] * wk;
        float wv = Wv[c * 64 + t]; g_Wf[2][c * 64 + t] = wv * skv[c];          av += okv[c] * wv;
    }
    g_bf[0][t] = scale * (bq[t] + aq);
    g_bf[1][t] = bk[t] + ak;
    g_bf[2][t] = bv[t] + av;
}

// ---------------- 4) projection, voxel-paired f32x2 -------------------------
// Block: 256 thr, tile 128 voxels. og = tid>>5 (8 output groups of 8 ch,
// UNIFORM within each warp -> all weight LDS are broadcasts), vp = tid&31
// (4 voxels = 2 f32x2 pairs per thread). Weights pre-duplicated (w,w) in smem
// at staging time -> the mainloop has ZERO pack/MOV ops: 5 LDS + 16*NPROJ
// FFMA2 per channel.
// sel: 0=q (skip->f_q), 1=kv (f_xu->f_k,f_v), 2=o (f_o->outext channel-first)
template <int NPROJ, bool CF_OUT>
__global__ __launch_bounds__(256) void proj2_kernel(int sel,
        const float* __restrict__ skip,
        const float* __restrict__ Wext, const float* __restrict__ bext,
        float* __restrict__ outext) {
    extern __shared__ char smem_raw[];
    u64*   sWd  = (u64*)smem_raw;                 // [NPROJ][64 c][64 ch] dup'd (32KB each)
    u64*   sBd  = sWd + NPROJ * 4096;             // [NPROJ][64] dup'd
    float* s_in = (float*)(sBd + NPROJ * 64);     // [64 c][128 vox] (32KB)

    const float* in;
    const float *W0, *b0, *W1 = nullptr, *b1 = nullptr;
    float *out0, *out1 = nullptr;
    if (sel == 0)      { in = skip; out0 = f_q; W0 = g_Wf[0]; b0 = g_bf[0]; }
    else if (sel == 1) { in = f_xu; out0 = f_k; out1 = f_v;
                         W0 = g_Wf[1]; b0 = g_bf[1]; W1 = g_Wf[2]; b1 = g_bf[2]; }
    else               { in = f_o;  out0 = outext; W0 = Wext; b0 = bext; }

    int tid = threadIdx.x;
    int vb  = blockIdx.x * 128;

    // stage weights duplicated
    for (int i = tid; i < 4096; i += 256) {
        sWd[i] = packdup(W0[i]);
        if (NPROJ == 2) sWd[4096 + i] = packdup(W1[i]);
    }
    if (tid < 64) {
        sBd[tid] = packdup(b0[tid]);
        if (NPROJ == 2) sBd[64 + tid] = packdup(b1[tid]);
    }
    // stage input tile [64][128], coalesced
    {
        int row = tid >> 5;           // 0..7
        int col = (tid & 31) * 4;     // 0..124
#pragma unroll
        for (int j = 0; j < 8; j++) {
            int r = row + j * 8;
            *(float4*)&s_in[r * 128 + col] = *(const float4*)(in + (size_t)r * NVOX + vb + col);
        }
    }
    __syncthreads();

    int og = tid >> 5;    // 0..7, uniform per warp
    int vp = tid & 31;    // 0..31, 4 voxels each

    const u64*   wp = sWd + og * 8;
    const float* ip = s_in + vp * 4;

    u64 acc[NPROJ][2][8];
#pragma unroll
    for (int p = 0; p < NPROJ; p++)
#pragma unroll
        for (int o = 0; o < 8; o++) {
            u64 b = sBd[p * 64 + og * 8 + o];
            acc[p][0][o] = b;
            acc[p][1][o] = b;
        }

#pragma unroll 4
    for (int c = 0; c < 64; c++) {
        ulonglong2 iv = *(const ulonglong2*)(ip + c * 128);   // pairs (v0,v1),(v2,v3)
        {
            const ulonglong2* wr = (const ulonglong2*)(wp + c * 64);
            ulonglong2 w01 = wr[0], w23 = wr[1], w45 = wr[2], w67 = wr[3];
            u64 wv[8] = {w01.x, w01.y, w23.x, w23.y, w45.x, w45.y, w67.x, w67.y};
#pragma unroll
            for (int o = 0; o < 8; o++) {
                acc[0][0][o] = ffma2(iv.x, wv[o], acc[0][0][o]);
                acc[0][1][o] = ffma2(iv.y, wv[o], acc[0][1][o]);
            }
        }
        if (NPROJ == 2) {
            const ulonglong2* wr = (const ulonglong2*)(wp + 4096 + c * 64);
            ulonglong2 w01 = wr[0], w23 = wr[1], w45 = wr[2], w67 = wr[3];
            u64 wv[8] = {w01.x, w01.y, w23.x, w23.y, w45.x, w45.y, w67.x, w67.y};
#pragma unroll
            for (int o = 0; o < 8; o++) {
                acc[1][0][o] = ffma2(iv.x, wv[o], acc[1][0][o]);
                acc[1][1][o] = ffma2(iv.y, wv[o], acc[1][1][o]);
            }
        }
    }

    if (!CF_OUT) {
        // voxel-major out[v*64 + ch]; acc[p][pr][o]: pr = voxel pair, lo/hi = even/odd voxel
#pragma unroll
        for (int p = 0; p < NPROJ; p++) {
            float* out = (p == 0) ? out0 : out1;
#pragma unroll
            for (int pr = 0; pr < 2; pr++) {
                int v0 = vb + vp * 4 + pr * 2;
                float4 e0 = make_float4(f2lo(acc[p][pr][0]), f2lo(acc[p][pr][1]), f2lo(acc[p][pr][2]), f2lo(acc[p][pr][3]));
                float4 e1 = make_float4(f2lo(acc[p][pr][4]), f2lo(acc[p][pr][5]), f2lo(acc[p][pr][6]), f2lo(acc[p][pr][7]));
                float4 d0 = make_float4(f2hi(acc[p][pr][0]), f2hi(acc[p][pr][1]), f2hi(acc[p][pr][2]), f2hi(acc[p][pr][3]));
                float4 d1 = make_float4(f2hi(acc[p][pr][4]), f2hi(acc[p][pr][5]), f2hi(acc[p][pr][6]), f2hi(acc[p][pr][7]));
                *(float4*)(out + (size_t)v0 * 64 + og * 8)           = e0;
                *(float4*)(out + (size_t)v0 * 64 + og * 8 + 4)       = e1;
                *(float4*)(out + (size_t)(v0 + 1) * 64 + og * 8)     = d0;
                *(float4*)(out + (size_t)(v0 + 1) * 64 + og * 8 + 4) = d1;
            }
        }
    } else {
        // channel-first: per channel a contiguous float4 of 4 voxels — natural layout
#pragma unroll
        for (int o = 0; o < 8; o++) {
            int ch = og * 8 + o;
            float4 r = make_float4(f2lo(acc[0][0][o]), f2hi(acc[0][0][o]),
                                   f2lo(acc[0][1][o]), f2hi(acc[0][1][o]));
            *(float4*)(out0 + (size_t)ch * NVOX + vb + vp * 4) = r;
        }
    }
}

// ---------------- 5) tiled neighborhood attention (f32x2 packed) ------------
__device__ __forceinline__ int sidx(int hl, int j) {
    return (hl * 2 + j) ^ (((hl >> 2) & 3) << 1);
}

__global__ __launch_bounds__(256) void attn_kernel(const float* __restrict__ rpb) {
    __shared__ float4 ks4[1216];
    __shared__ float4 vs4[1216];
    __shared__ float bias_s[125];

    int tid  = threadIdx.x;
    int tb   = blockIdx.x;          // 0..255 : 8x8x4 tiles
    int head = blockIdx.y;
    int h0 = (tb >> 5) * 8;
    int w0 = ((tb >> 2) & 7) * 8;
    int z0 = (tb & 3) * 4;

    for (int i = tid; i < 600; i += 256) {
        int ah = i / 60; int r = i - ah * 60; int aw = r / 6; int az = r - aw * 6;
        int gh = min(max(h0 - 1 + ah, 0), 63);
        int gw = min(max(w0 - 1 + aw, 0), 63);
        int gz = min(max(z0 - 1 + az, 0), 15);
        int gv = ((gh << 6) + gw) * 16 + gz;
        const float4* pk = (const float4*)(f_k + (size_t)gv * 64 + head * 8);
        ks4[sidx(i, 0)] = pk[0];
        ks4[sidx(i, 1)] = pk[1];
        const float4* pv = (const float4*)(f_v + (size_t)gv * 64 + head * 8);
        vs4[sidx(i, 0)] = pv[0];
        vs4[sidx(i, 1)] = pv[1];
    }
    if (tid < 125) bias_s[tid] = rpb[head * 125 + tid];
    __syncthreads();

    int lth = tid >> 5;
    int ltw = (tid >> 2) & 7;
    int ltz = tid & 3;
    int h = h0 + lth, w = w0 + ltw, z = z0 + ltz;
    int v = ((h << 6) + w) * 16 + z;

    const ulonglong2* pq = (const ulonglong2*)(f_q + (size_t)v * 64 + head * 8);
    ulonglong2 qa = pq[0], qb = pq[1];   // q pairs: (0,1)(2,3)(4,5)(6,7)

    int sh = min(max(h - 1, 0), 61);
    int sw = min(max(w - 1, 0), 61);
    int sz = min(max(z - 1, 0), 13);
    int lhh = sh - h0 + 1, lww = sw - w0 + 1, lzz = sz - z0 + 1;
    int rb = (sh - h + 2) * 25 + (sw - w + 2) * 5 + (sz - z + 2);

    float logits[27];
    int   hls[27];
    float mx = -1e30f;
#pragma unroll
    for (int a = 0; a < 3; a++)
#pragma unroll
    for (int b = 0; b < 3; b++)
#pragma unroll
    for (int cc = 0; cc < 3; cc++) {
        int m  = (a * 3 + b) * 3 + cc;
        int hl = ((lhh + a) * 10 + (lww + b)) * 6 + (lzz + cc);
        hls[m] = hl;
        ulonglong2 ka = *(const ulonglong2*)&ks4[sidx(hl, 0)];
        ulonglong2 kb = *(const ulonglong2*)&ks4[sidx(hl, 1)];
        u64 d2 = fmul2(qa.x, ka.x);
        d2 = ffma2(qa.y, ka.y, d2);
        d2 = ffma2(qb.x, kb.x, d2);
        d2 = ffma2(qb.y, kb.y, d2);
        float d = f2lo(d2) + f2hi(d2) + bias_s[rb + a * 25 + b * 5 + cc];
        logits[m] = d;
        mx = fmaxf(mx, d);
    }
    float ssum = 0.f;
#pragma unroll
    for (int m = 0; m < 27; m++) {
        float e = __expf(logits[m] - mx);
        logits[m] = e;
        ssum += e;
    }
    float inv = 1.0f / ssum;
    u64 o01 = 0, o23 = 0, o45 = 0, o67 = 0;   // 0x0 == (+0.f, +0.f)
#pragma unroll
    for (int m = 0; m < 27; m++) {
        u64 a2 = packdup(logits[m] * inv);
        ulonglong2 va = *(const ulonglong2*)&vs4[sidx(hls[m], 0)];
        ulonglong2 vb = *(const ulonglong2*)&vs4[sidx(hls[m], 1)];
        o01 = ffma2(a2, va.x, o01);
        o23 = ffma2(a2, va.y, o23);
        o45 = ffma2(a2, vb.x, o45);
        o67 = ffma2(a2, vb.y, o67);
    }
    int cb = head * 8;
    f_o[(size_t)(cb + 0) * NVOX + v] = f2lo(o01);
    f_o[(size_t)(cb + 1) * NVOX + v] = f2hi(o01);
    f_o[(size_t)(cb + 2) * NVOX + v] = f2lo(o23);
    f_o[(size_t)(cb + 3) * NVOX + v] = f2hi(o23);
    f_o[(size_t)(cb + 4) * NVOX + v] = f2lo(o45);
    f_o[(size_t)(cb + 5) * NVOX + v] = f2hi(o45);
    f_o[(size_t)(cb + 6) * NVOX + v] = f2lo(o67);
    f_o[(size_t)(cb + 7) * NVOX + v] = f2hi(o67);
}

// ---------------------------------------------------------------------------
extern "C" void kernel_launch(void* const* d_in, const int* in_sizes, int n_in,
                              void* d_out, int out_size) {
    const float* x    = (const float*)d_in[0];
    const float* skip = (const float*)d_in[1];
    const float* Wq   = (const float*)d_in[2];
    const float* bq   = (const float*)d_in[3];
    const float* Wk   = (const float*)d_in[4];
    const float* bk   = (const float*)d_in[5];
    const float* Wv   = (const float*)d_in[6];
    const float* bv   = (const float*)d_in[7];
    const float* Wo   = (const float*)d_in[8];
    const float* bo   = (const float*)d_in[9];
    const float* rpb  = (const float*)d_in[10];
    float* out = (float*)d_out;

    const int SMEM1 = 4096 * 8 + 64 * 8 + 64 * 128 * 4;       // 66048 B
    const int SMEM2 = 2 * (4096 * 8 + 64 * 8) + 64 * 128 * 4; // 99328 B
    cudaFuncSetAttribute(proj2_kernel<1, false>, cudaFuncAttributeMaxDynamicSharedMemorySize, SMEM1);
    cudaFuncSetAttribute(proj2_kernel<2, false>, cudaFuncAttributeMaxDynamicSharedMemorySize, SMEM2);
    cudaFuncSetAttribute(proj2_kernel<1, true>,  cudaFuncAttributeMaxDynamicSharedMemorySize, SMEM1);

    upsample_kernel<<<dim3(256, 8), 256>>>(x);
    stats_kernel<<<512, 256>>>(skip);
    fold_kernel<<<1, 64>>>(Wq, bq, Wk, bk, Wv, bv);
    proj2_kernel<1, false><<<512, 256, SMEM1>>>(0, skip, nullptr, nullptr, nullptr);  // q
    proj2_kernel<2, false><<<512, 256, SMEM2>>>(1, skip, nullptr, nullptr, nullptr);  // k+v
    attn_kernel<<<dim3(256, 8), 256>>>(rpb);
    proj2_kernel<1, true><<<512, 256, SMEM1>>>(2, skip, Wo, bo, out);                 // o
}

// round 12
// speedup vs baseline: 1.0568x; 1.0568x over previous
#include <cuda_runtime.h>
#include <cuda_bf16.h>
#include <math.h>

#define NVOX 65536            // 64*64*16 voxels
#define CCH 64
#define NHEAD 8
#define DHEAD 8

typedef unsigned long long u64;

// ---------------- scratch (device globals; no allocation allowed) ----------
__device__ float f_xu[CCH * NVOX];   // upsampled x, channel-first [c][v]
__device__ float f_q[NVOX * CCH];    // q projection, voxel-major [v][c]
__device__ float f_k[NVOX * CCH];
__device__ float f_v[NVOX * CCH];
__device__ float f_o[CCH * NVOX];    // attention output, channel-first [c][v]
__device__ float g_psum[512], g_psumsq[512];   // [0:256] xu quarters, [256:512] skip quarters
// packed bf16-split weight tiles in FINAL swizzled smem-image layout,
// [n=64][k'=192] K-contiguous rows of 384B; 24576 B each. 0=q 1=k 2=v 3=o
__device__ uint4 g_Wbf[4 * 1536];
__device__ float g_bf4[4][CCH];

// ---------------- helpers ---------------------------------------------------
__device__ __forceinline__ unsigned smem_u32(const void* p) {
    unsigned a;
    asm("{ .reg .u64 t; cvta.to.shared.u64 t, %1; cvt.u32.u64 %0, t; }" : "=r"(a) : "l"(p));
    return a;
}
// XOR swizzle on 16B lanes within 128B segments; rows are 384B (3 segs) so
// consecutive rows shift the pattern by 3 (coprime to 8) -> conflict-free
// column access for ldmatrix/STS.128.
__host__ __device__ __forceinline__ unsigned swz(unsigned off) {
    return off ^ (((off >> 7) & 7u) << 4);
}
#define LDSM4(r0, r1, r2, r3, addr) \
    asm volatile("ldmatrix.sync.aligned.m8n8.x4.shared.b16 {%0,%1,%2,%3}, [%4];" \
                 : "=r"(r0), "=r"(r1), "=r"(r2), "=r"(r3) : "r"(addr))
#define MMA16816(d, a0, a1, a2, a3, b0, b1) \
    asm volatile("mma.sync.aligned.m16n8k16.row.col.f32.bf16.bf16.f32 " \
                 "{%0,%1,%2,%3}, {%4,%5,%6,%7}, {%8,%9}, {%0,%1,%2,%3};" \
                 : "+f"((d)[0]), "+f"((d)[1]), "+f"((d)[2]), "+f"((d)[3]) \
                 : "r"(a0), "r"(a1), "r"(a2), "r"(a3), "r"(b0), "r"(b1))

__device__ __forceinline__ u64 ffma2(u64 a, u64 b, u64 c) {
    u64 d;
    asm("fma.rn.f32x2 %0, %1, %2, %3;" : "=l"(d) : "l"(a), "l"(b), "l"(c));
    return d;
}
__device__ __forceinline__ u64 fmul2(u64 a, u64 b) {
    u64 d;
    asm("mul.rn.f32x2 %0, %1, %2;" : "=l"(d) : "l"(a), "l"(b));
    return d;
}
__device__ __forceinline__ u64 packdup(float w) {
    unsigned u = __float_as_uint(w);
    return ((u64)u << 32) | (u64)u;
}
__device__ __forceinline__ float f2lo(u64 a) { return __uint_as_float((unsigned)a); }
__device__ __forceinline__ float f2hi(u64 a) { return __uint_as_float((unsigned)(a >> 32)); }

// ---------------- 1) trilinear upsample ------------------------------------
__global__ __launch_bounds__(256) void upsample_kernel(const float* __restrict__ x) {
    int v = blockIdx.x * 256 + threadIdx.x;
    int h = v >> 10;
    int w = (v >> 4) & 63;
    int z = v & 15;

    const float rh = (float)(31.0 / 63.0);
    const float rw = (float)(31.0 / 63.0);
    const float rz = (float)(7.0 / 15.0);

    float ph = (float)h * rh; int ih = (int)ph; if (ih > 30) ih = 30; float fh = ph - (float)ih;
    float pw = (float)w * rw; int iw = (int)pw; if (iw > 30) iw = 30; float fw = pw - (float)iw;
    float pz = (float)z * rz; int iz = (int)pz; if (iz > 6)  iz = 6;  float fz = pz - (float)iz;

    int base = ih * 256 + iw * 8 + iz;
    int cbase = blockIdx.y * 8;

#pragma unroll
    for (int ci = 0; ci < 8; ci++) {
        int c = cbase + ci;
        const float* xc = x + c * 8192 + base;
        float c000 = xc[0],   c100 = xc[256], c010 = xc[8],   c110 = xc[264];
        float c001 = xc[1],   c101 = xc[257], c011 = xc[9],   c111 = xc[265];
        float a00 = c000 + fh * (c100 - c000);
        float a10 = c010 + fh * (c110 - c010);
        float a01 = c001 + fh * (c101 - c001);
        float a11 = c011 + fh * (c111 - c011);
        float b0  = a00 + fw * (a10 - a00);
        float b1  = a01 + fw * (a11 - a01);
        f_xu[c * NVOX + v] = b0 + fz * (b1 - b0);
    }
}

// ---------------- 2) per-channel partial stats -----------------------------
__global__ __launch_bounds__(256) void stats_kernel(const float* __restrict__ skip) {
    int b = blockIdx.x;   // 0..511
    const int quart = NVOX / 4;
    const float* p;
    if (b < 256) p = f_xu + (b >> 2) * NVOX + (b & 3) * quart;
    else         p = skip + ((b - 256) >> 2) * NVOX + (b & 3) * quart;

    const float4* p4 = (const float4*)p;
    float s = 0.f, s2 = 0.f;
    for (int i = threadIdx.x; i < quart / 4; i += 256) {
        float4 val = p4[i];
        s  += val.x + val.y + val.z + val.w;
        s2 += val.x * val.x + val.y * val.y + val.z * val.z + val.w * val.w;
    }
    __shared__ float sh1[256], sh2[256];
    sh1[threadIdx.x] = s; sh2[threadIdx.x] = s2;
    __syncthreads();
    for (int off = 128; off > 0; off >>= 1) {
        if (threadIdx.x < off) {
            sh1[threadIdx.x] += sh1[threadIdx.x + off];
            sh2[threadIdx.x] += sh2[threadIdx.x + off];
        }
        __syncthreads();
    }
    if (threadIdx.x == 0) { g_psum[b] = sh1[0]; g_psumsq[b] = sh2[0]; }
}

// ---------------- 3) fold norm into weights; emit packed bf16 tiles --------
__global__ __launch_bounds__(256) void fold_kernel(
        const float* __restrict__ Wq, const float* __restrict__ bq,
        const float* __restrict__ Wk, const float* __restrict__ bk,
        const float* __restrict__ Wv, const float* __restrict__ bv,
        const float* __restrict__ Wo, const float* __restrict__ bo) {
    __shared__ float skv[64], okv[64], sq_[64], oq_[64];
    int t = threadIdx.x;
    const float invN = 1.0f / 65536.0f;
    const float scale = 0.3535533905932738f;  // dh^-0.5
    if (t < 64) {
        float m  = (g_psum[4 * t] + g_psum[4 * t + 1] + g_psum[4 * t + 2] + g_psum[4 * t + 3]) * invN;
        float va = (g_psumsq[4 * t] + g_psumsq[4 * t + 1] + g_psumsq[4 * t + 2] + g_psumsq[4 * t + 3]) * invN - m * m;
        float sc = rsqrtf(va + 1e-5f);
        skv[t] = sc; okv[t] = -m * sc;
        m  = (g_psum[256 + 4 * t] + g_psum[257 + 4 * t] + g_psum[258 + 4 * t] + g_psum[259 + 4 * t]) * invN;
        va = (g_psumsq[256 + 4 * t] + g_psumsq[257 + 4 * t] + g_psumsq[258 + 4 * t] + g_psumsq[259 + 4 * t]) * invN - m * m;
        sc = rsqrtf(va + 1e-5f);
        sq_[t] = sc; oq_[t] = -m * sc;
    }
    __syncthreads();
    if (t < 64) {
        float aq = 0.f, ak = 0.f, av = 0.f;
        for (int c = 0; c < 64; c++) {
            aq += oq_[c] * Wq[c * 64 + t];
            ak += okv[c] * Wk[c * 64 + t];
            av += okv[c] * Wv[c * 64 + t];
        }
        g_bf4[0][t] = scale * (bq[t] + aq);
        g_bf4[1][t] = bk[t] + ak;
        g_bf4[2][t] = bv[t] + av;
        g_bf4[3][t] = bo[t];
    }
    __syncthreads();

    // pack weights: rows n (output), cols k' = [Whi | Whi | Wlo], swizzled
    for (int p = 0; p < 4; p++) {
        const float* W = (p == 0) ? Wq : (p == 1) ? Wk : (p == 2) ? Wv : Wo;
        unsigned char* dst = (unsigned char*)g_Wbf + p * 24576;
        for (int idx = t; idx < 4096; idx += 256) {
            int c = idx >> 6, n = idx & 63;     // c = input channel (k), n = output
            float w = W[c * 64 + n];
            if (p == 0)      w *= sq_[c] * scale;
            else if (p < 3)  w *= skv[c];
            __nv_bfloat16 h = __float2bfloat16(w);
            float r = w - __bfloat162float(h);
            unsigned short hu = __bfloat16_as_ushort(h);
            unsigned short lu = __bfloat16_as_ushort(__float2bfloat16(r));
            *(unsigned short*)(dst + swz(n * 384u + (unsigned)c * 2u))         = hu;
            *(unsigned short*)(dst + swz(n * 384u + (unsigned)(64 + c) * 2u))  = hu;
            *(unsigned short*)(dst + swz(n * 384u + (unsigned)(128 + c) * 2u)) = lu;
        }
    }
}

// ---------------- 4) warp-MMA projection ------------------------------------
// 256 threads = 8 warps; tile M=128 voxels, N=64 outputs, K'=192 (bf16 split
// [hi|lo|hi] x [Whi|Whi|Wlo]).  Each warp: one 16-voxel m-tile, 8 n-tiles,
// 12 k-tiles of mma.sync.m16n8k16.bf16.  SEL: 0=q(skip->f_q) 1=kv(f_xu->f_k,f_v)
// 2=o(f_o->outext channel-first via smem bounce).
template <int NPROJ, int SEL>
__global__ __launch_bounds__(256) void proj_mma(const float* __restrict__ skip,
                                                float* __restrict__ outext) {
    extern __shared__ char smem[];          // [0,49152): A  [49152,+NPROJ*24576): B, then bias
    float* sBias = (float*)(smem + 49152 + NPROJ * 24576);

    const int tid = threadIdx.x;
    const int l = tid & 31, w = tid >> 5;
    const int vb = blockIdx.x * 128;
    const int wsel = (SEL == 0) ? 0 : (SEL == 1) ? 1 : 3;
    const float* in = (SEL == 0) ? skip : (SEL == 1) ? f_xu : f_o;

    // stage B (linear copy of pre-swizzled image)
    {
        const uint4* src = g_Wbf + wsel * 1536;
        uint4* dst = (uint4*)(smem + 49152);
        for (int i = tid; i < NPROJ * 1536; i += 256) dst[i] = src[i];
    }
    if (tid < NPROJ * 64) sBias[tid] = g_bf4[wsel + (tid >> 6)][tid & 63];

    // stage A: each thread = one voxel row half (32 channels)
    {
        int vox = tid & 127;
        int hh = tid >> 7;
        float xv[32];
#pragma unroll
        for (int j = 0; j < 32; j++)
            xv[j] = in[(size_t)(hh * 32 + j) * NVOX + vb + vox];
        unsigned rowb = (unsigned)vox * 384u;
#pragma unroll
        for (int g = 0; g < 4; g++) {
            unsigned hp[4], lp[4];
#pragma unroll
            for (int e = 0; e < 4; e++) {
                float a = xv[g * 8 + 2 * e], b = xv[g * 8 + 2 * e + 1];
                __nv_bfloat16 ha = __float2bfloat16(a), hb = __float2bfloat16(b);
                float ra = a - __bfloat162float(ha);
                float rb = b - __bfloat162float(hb);
                hp[e] = ((unsigned)__bfloat16_as_ushort(hb) << 16) | __bfloat16_as_ushort(ha);
                lp[e] = ((unsigned)__bfloat16_as_ushort(__float2bfloat16(rb)) << 16)
                      | (unsigned)__bfloat16_as_ushort(__float2bfloat16(ra));
            }
            unsigned cb = (unsigned)(hh * 64 + g * 16);
            *(uint4*)(smem + swz(rowb + cb))        = make_uint4(hp[0], hp[1], hp[2], hp[3]);
            *(uint4*)(smem + swz(rowb + 128u + cb)) = make_uint4(lp[0], lp[1], lp[2], lp[3]);
            *(uint4*)(smem + swz(rowb + 256u + cb)) = make_uint4(hp[0], hp[1], hp[2], hp[3]);
        }
    }
    __syncthreads();

    const unsigned sAu = smem_u32(smem);
    const unsigned sBu = sAu + 49152;
    const int m0 = w * 16;
    // ldmatrix source coords (A: 16x16 from [m][k]; B: two 16x8 from [n][k])
    const unsigned arow = (unsigned)(m0 + (l & 7) + ((l >> 3) & 1) * 8);
    const unsigned acolb = (unsigned)((l >> 4) * 16);          // bytes
    const unsigned brow = (unsigned)((l & 7) + ((l >> 4) & 1) * 8);
    const unsigned bcolb = (unsigned)(((l >> 3) & 1) * 16);    // bytes

    float acc[NPROJ][8][4];
#pragma unroll
    for (int p = 0; p < NPROJ; p++)
#pragma unroll
        for (int nt = 0; nt < 8; nt++)
#pragma unroll
            for (int e = 0; e < 4; e++) acc[p][nt][e] = 0.f;

#pragma unroll
    for (int kt = 0; kt < 12; kt++) {
        unsigned kb = (unsigned)kt * 32u;     // 16 elements * 2B
        unsigned a0, a1, a2, a3;
        LDSM4(a0, a1, a2, a3, sAu + swz(arow * 384u + kb + acolb));
#pragma unroll
        for (int ntp = 0; ntp < 4; ntp++) {
#pragma unroll
            for (int p = 0; p < NPROJ; p++) {
                unsigned b0, b1, b2, b3;
                unsigned baddr = sBu + (unsigned)p * 24576u
                               + swz(((unsigned)(ntp * 16) + brow) * 384u + kb + bcolb);
                LDSM4(b0, b1, b2, b3, baddr);
                MMA16816(acc[p][2 * ntp],     a0, a1, a2, a3, b0, b1);
                MMA16816(acc[p][2 * ntp + 1], a0, a1, a2, a3, b2, b3);
            }
        }
    }

    const int gid = l >> 2, tig = l & 3;
    if (SEL != 2) {
#pragma unroll
        for (int p = 0; p < NPROJ; p++) {
            float* out = (SEL == 0) ? f_q : (p == 0 ? f_k : f_v);
            size_t r0b = (size_t)(vb + m0 + gid) * 64;
            size_t r1b = (size_t)(vb + m0 + gid + 8) * 64;
#pragma unroll
            for (int nt = 0; nt < 8; nt++) {
                int ch = nt * 8 + tig * 2;
                float2 v0, v1;
                v0.x = acc[p][nt][0] + sBias[p * 64 + ch];
                v0.y = acc[p][nt][1] + sBias[p * 64 + ch + 1];
                v1.x = acc[p][nt][2] + sBias[p * 64 + ch];
                v1.y = acc[p][nt][3] + sBias[p * 64 + ch + 1];
                *(float2*)(out + r0b + ch) = v0;
                *(float2*)(out + r1b + ch) = v1;
            }
        }
    } else {
        // channel-first bounce: sOut[64][132] (pad -> conflict-free)
        __syncthreads();
        float* sOut = (float*)smem;
#pragma unroll
        for (int nt = 0; nt < 8; nt++) {
            int ch = nt * 8 + tig * 2;
            int v0 = m0 + gid, v1 = v0 + 8;
            sOut[ch * 132 + v0]       = acc[0][nt][0] + sBias[ch];
            sOut[(ch + 1) * 132 + v0] = acc[0][nt][1] + sBias[ch + 1];
            sOut[ch * 132 + v1]       = acc[0][nt][2] + sBias[ch];
            sOut[(ch + 1) * 132 + v1] = acc[0][nt][3] + sBias[ch + 1];
        }
        __syncthreads();
        for (int i = tid; i < 64 * 32; i += 256) {
            int ch = i >> 5, vv = (i & 31) * 4;
            float4 o4;
            o4.x = sOut[ch * 132 + vv];
            o4.y = sOut[ch * 132 + vv + 1];
            o4.z = sOut[ch * 132 + vv + 2];
            o4.w = sOut[ch * 132 + vv + 3];
            *(float4*)(outext + (size_t)ch * NVOX + vb + vv) = o4;
        }
    }
}

// ---------------- 5) tiled neighborhood attention (f32x2 packed) ------------
__device__ __forceinline__ int sidx(int hl, int j) {
    return (hl * 2 + j) ^ (((hl >> 2) & 3) << 1);
}

__global__ __launch_bounds__(256) void attn_kernel(const float* __restrict__ rpb) {
    __shared__ float4 ks4[1216];
    __shared__ float4 vs4[1216];
    __shared__ float bias_s[125];

    int tid  = threadIdx.x;
    int tb   = blockIdx.x;          // 0..255 : 8x8x4 tiles
    int head = blockIdx.y;
    int h0 = (tb >> 5) * 8;
    int w0 = ((tb >> 2) & 7) * 8;
    int z0 = (tb & 3) * 4;

    for (int i = tid; i < 600; i += 256) {
        int ah = i / 60; int r = i - ah * 60; int aw = r / 6; int az = r - aw * 6;
        int gh = min(max(h0 - 1 + ah, 0), 63);
        int gw = min(max(w0 - 1 + aw, 0), 63);
        int gz = min(max(z0 - 1 + az, 0), 15);
        int gv = ((gh << 6) + gw) * 16 + gz;
        const float4* pk = (const float4*)(f_k + (size_t)gv * 64 + head * 8);
        ks4[sidx(i, 0)] = pk[0];
        ks4[sidx(i, 1)] = pk[1];
        const float4* pv = (const float4*)(f_v + (size_t)gv * 64 + head * 8);
        vs4[sidx(i, 0)] = pv[0];
        vs4[sidx(i, 1)] = pv[1];
    }
    if (tid < 125) bias_s[tid] = rpb[head * 125 + tid];
    __syncthreads();

    int lth = tid >> 5;
    int ltw = (tid >> 2) & 7;
    int ltz = tid & 3;
    int h = h0 + lth, w = w0 + ltw, z = z0 + ltz;
    int v = ((h << 6) + w) * 16 + z;

    const ulonglong2* pq = (const ulonglong2*)(f_q + (size_t)v * 64 + head * 8);
    ulonglong2 qa = pq[0], qb = pq[1];

    int sh = min(max(h - 1, 0), 61);
    int sw = min(max(w - 1, 0), 61);
    int sz = min(max(z - 1, 0), 13);
    int lhh = sh - h0 + 1, lww = sw - w0 + 1, lzz = sz - z0 + 1;
    int rb = (sh - h + 2) * 25 + (sw - w + 2) * 5 + (sz - z + 2);

    float logits[27];
    int   hls[27];
    float mx = -1e30f;
#pragma unroll
    for (int a = 0; a < 3; a++)
#pragma unroll
    for (int b = 0; b < 3; b++)
#pragma unroll
    for (int cc = 0; cc < 3; cc++) {
        int m  = (a * 3 + b) * 3 + cc;
        int hl = ((lhh + a) * 10 + (lww + b)) * 6 + (lzz + cc);
        hls[m] = hl;
        ulonglong2 ka = *(const ulonglong2*)&ks4[sidx(hl, 0)];
        ulonglong2 kb = *(const ulonglong2*)&ks4[sidx(hl, 1)];
        u64 d2 = fmul2(qa.x, ka.x);
        d2 = ffma2(qa.y, ka.y, d2);
        d2 = ffma2(qb.x, kb.x, d2);
        d2 = ffma2(qb.y, kb.y, d2);
        float d = f2lo(d2) + f2hi(d2) + bias_s[rb + a * 25 + b * 5 + cc];
        logits[m] = d;
        mx = fmaxf(mx, d);
    }
    float ssum = 0.f;
#pragma unroll
    for (int m = 0; m < 27; m++) {
        float e = __expf(logits[m] - mx);
        logits[m] = e;
        ssum += e;
    }
    float inv = 1.0f / ssum;
    u64 o01 = 0, o23 = 0, o45 = 0, o67 = 0;
#pragma unroll
    for (int m = 0; m < 27; m++) {
        u64 a2 = packdup(logits[m] * inv);
        ulonglong2 va = *(const ulonglong2*)&vs4[sidx(hls[m], 0)];
        ulonglong2 vb = *(const ulonglong2*)&vs4[sidx(hls[m], 1)];
        o01 = ffma2(a2, va.x, o01);
        o23 = ffma2(a2, va.y, o23);
        o45 = ffma2(a2, vb.x, o45);
        o67 = ffma2(a2, vb.y, o67);
    }
    int cb = head * 8;
    f_o[(size_t)(cb + 0) * NVOX + v] = f2lo(o01);
    f_o[(size_t)(cb + 1) * NVOX + v] = f2hi(o01);
    f_o[(size_t)(cb + 2) * NVOX + v] = f2lo(o23);
    f_o[(size_t)(cb + 3) * NVOX + v] = f2hi(o23);
    f_o[(size_t)(cb + 4) * NVOX + v] = f2lo(o45);
    f_o[(size_t)(cb + 5) * NVOX + v] = f2hi(o45);
    f_o[(size_t)(cb + 6) * NVOX + v] = f2lo(o67);
    f_o[(size_t)(cb + 7) * NVOX + v] = f2hi(o67);
}

// ---------------------------------------------------------------------------
extern "C" void kernel_launch(void* const* d_in, const int* in_sizes, int n_in,
                              void* d_out, int out_size) {
    const float* x    = (const float*)d_in[0];
    const float* skip = (const float*)d_in[1];
    const float* Wq   = (const float*)d_in[2];
    const float* bq   = (const float*)d_in[3];
    const float* Wk   = (const float*)d_in[4];
    const float* bk   = (const float*)d_in[5];
    const float* Wv   = (const float*)d_in[6];
    const float* bv   = (const float*)d_in[7];
    const float* Wo   = (const float*)d_in[8];
    const float* bo   = (const float*)d_in[9];
    const float* rpb  = (const float*)d_in[10];
    float* out = (float*)d_out;

    const int SMEM1 = 49152 + 24576 + 512;       // 74240
    const int SMEM2 = 49152 + 2 * 24576 + 512;   // 98816
    cudaFuncSetAttribute(proj_mma<1, 0>, cudaFuncAttributeMaxDynamicSharedMemorySize, SMEM1);
    cudaFuncSetAttribute(proj_mma<2, 1>, cudaFuncAttributeMaxDynamicSharedMemorySize, SMEM2);
    cudaFuncSetAttribute(proj_mma<1, 2>, cudaFuncAttributeMaxDynamicSharedMemorySize, SMEM1);

    upsample_kernel<<<dim3(256, 8), 256>>>(x);
    stats_kernel<<<512, 256>>>(skip);
    fold_kernel<<<1, 256>>>(Wq, bq, Wk, bk, Wv, bv, Wo, bo);
    proj_mma<1, 0><<<512, 256, SMEM1>>>(skip, nullptr);   // q
    proj_mma<2, 1><<<512, 256, SMEM2>>>(skip, nullptr);   // k + v
    attn_kernel<<<dim3(256, 8), 256>>>(rpb);
    proj_mma<1, 2><<<512, 256, SMEM1>>>(skip, out);       // o
}

// round 13
// speedup vs baseline: 1.4547x; 1.3765x over previous
#include <cuda_runtime.h>
#include <cuda_bf16.h>
#include <math.h>

#define NVOX 65536            // 64*64*16 voxels
#define CCH 64
#define NHEAD 8
#define DHEAD 8

typedef unsigned long long u64;

// ---------------- scratch (device globals; no allocation allowed) ----------
__device__ float f_xu[CCH * NVOX];   // upsampled x, channel-first [c][v]
// head-major attention tensors: [head][vox][8]
__device__ float f_q[NHEAD * NVOX * DHEAD];
__device__ float f_k[NHEAD * NVOX * DHEAD];
__device__ float f_v[NHEAD * NVOX * DHEAD];
__device__ float f_o[NHEAD * NVOX * DHEAD];
__device__ float g_psum[512], g_psumsq[512];   // [0:256] xu quarters, [256:512] skip quarters
// packed bf16-split weight tiles in FINAL swizzled smem-image layout,
// [n=64][k'=192] K-contiguous rows of 384B; 24576 B each. 0=q 1=k 2=v 3=o
__device__ uint4 g_Wbf[4 * 1536];
__device__ float g_bf4[4][CCH];

// ---------------- helpers ---------------------------------------------------
__device__ __forceinline__ unsigned smem_u32(const void* p) {
    unsigned a;
    asm("{ .reg .u64 t; cvta.to.shared.u64 t, %1; cvt.u32.u64 %0, t; }" : "=r"(a) : "l"(p));
    return a;
}
// XOR swizzle on 16B lanes within 128B segments; rows are 384B (3 segs) so
// consecutive rows shift the pattern by 3 (coprime to 8) -> conflict-free
// column access for ldmatrix/STS.128.
__host__ __device__ __forceinline__ unsigned swz(unsigned off) {
    return off ^ (((off >> 7) & 7u) << 4);
}
#define LDSM4(r0, r1, r2, r3, addr) \
    asm volatile("ldmatrix.sync.aligned.m8n8.x4.shared.b16 {%0,%1,%2,%3}, [%4];" \
                 : "=r"(r0), "=r"(r1), "=r"(r2), "=r"(r3) : "r"(addr))
#define MMA16816(d, a0, a1, a2, a3, b0, b1) \
    asm volatile("mma.sync.aligned.m16n8k16.row.col.f32.bf16.bf16.f32 " \
                 "{%0,%1,%2,%3}, {%4,%5,%6,%7}, {%8,%9}, {%0,%1,%2,%3};" \
                 : "+f"((d)[0]), "+f"((d)[1]), "+f"((d)[2]), "+f"((d)[3]) \
                 : "r"(a0), "r"(a1), "r"(a2), "r"(a3), "r"(b0), "r"(b1))

__device__ __forceinline__ u64 ffma2(u64 a, u64 b, u64 c) {
    u64 d;
    asm("fma.rn.f32x2 %0, %1, %2, %3;" : "=l"(d) : "l"(a), "l"(b), "l"(c));
    return d;
}
__device__ __forceinline__ u64 fmul2(u64 a, u64 b) {
    u64 d;
    asm("mul.rn.f32x2 %0, %1, %2;" : "=l"(d) : "l"(a), "l"(b));
    return d;
}
__device__ __forceinline__ u64 packdup(float w) {
    unsigned u = __float_as_uint(w);
    return ((u64)u << 32) | (u64)u;
}
__device__ __forceinline__ float f2lo(u64 a) { return __uint_as_float((unsigned)a); }
__device__ __forceinline__ float f2hi(u64 a) { return __uint_as_float((unsigned)(a >> 32)); }

// ---------------- 1) trilinear upsample ------------------------------------
__global__ __launch_bounds__(256) void upsample_kernel(const float* __restrict__ x) {
    int v = blockIdx.x * 256 + threadIdx.x;
    int h = v >> 10;
    int w = (v >> 4) & 63;
    int z = v & 15;

    const float rh = (float)(31.0 / 63.0);
    const float rw = (float)(31.0 / 63.0);
    const float rz = (float)(7.0 / 15.0);

    float ph = (float)h * rh; int ih = (int)ph; if (ih > 30) ih = 30; float fh = ph - (float)ih;
    float pw = (float)w * rw; int iw = (int)pw; if (iw > 30) iw = 30; float fw = pw - (float)iw;
    float pz = (float)z * rz; int iz = (int)pz; if (iz > 6)  iz = 6;  float fz = pz - (float)iz;

    int base = ih * 256 + iw * 8 + iz;
    int cbase = blockIdx.y * 8;

#pragma unroll
    for (int ci = 0; ci < 8; ci++) {
        int c = cbase + ci;
        const float* xc = x + c * 8192 + base;
        float c000 = xc[0],   c100 = xc[256], c010 = xc[8],   c110 = xc[264];
        float c001 = xc[1],   c101 = xc[257], c011 = xc[9],   c111 = xc[265];
        float a00 = c000 + fh * (c100 - c000);
        float a10 = c010 + fh * (c110 - c010);
        float a01 = c001 + fh * (c101 - c001);
        float a11 = c011 + fh * (c111 - c011);
        float b0  = a00 + fw * (a10 - a00);
        float b1  = a01 + fw * (a11 - a01);
        f_xu[c * NVOX + v] = b0 + fz * (b1 - b0);
    }
}

// ---------------- 2) per-channel partial stats -----------------------------
__global__ __launch_bounds__(256) void stats_kernel(const float* __restrict__ skip) {
    int b = blockIdx.x;   // 0..511
    const int quart = NVOX / 4;
    const float* p;
    if (b < 256) p = f_xu + (b >> 2) * NVOX + (b & 3) * quart;
    else         p = skip + ((b - 256) >> 2) * NVOX + (b & 3) * quart;

    const float4* p4 = (const float4*)p;
    float s = 0.f, s2 = 0.f;
    for (int i = threadIdx.x; i < quart / 4; i += 256) {
        float4 val = p4[i];
        s  += val.x + val.y + val.z + val.w;
        s2 += val.x * val.x + val.y * val.y + val.z * val.z + val.w * val.w;
    }
    __shared__ float sh1[256], sh2[256];
    sh1[threadIdx.x] = s; sh2[threadIdx.x] = s2;
    __syncthreads();
    for (int off = 128; off > 0; off >>= 1) {
        if (threadIdx.x < off) {
            sh1[threadIdx.x] += sh1[threadIdx.x + off];
            sh2[threadIdx.x] += sh2[threadIdx.x + off];
        }
        __syncthreads();
    }
    if (threadIdx.x == 0) { g_psum[b] = sh1[0]; g_psumsq[b] = sh2[0]; }
}

// ---------------- 3) fold norm into weights; emit packed bf16 tiles --------
__global__ __launch_bounds__(256) void fold_kernel(
        const float* __restrict__ Wq, const float* __restrict__ bq,
        const float* __restrict__ Wk, const float* __restrict__ bk,
        const float* __restrict__ Wv, const float* __restrict__ bv,
        const float* __restrict__ Wo, const float* __restrict__ bo) {
    __shared__ float skv[64], okv[64], sq_[64], oq_[64];
    __shared__ unsigned char spack[24576];
    int t = threadIdx.x;
    const float invN = 1.0f / 65536.0f;
    const float scale = 0.3535533905932738f;  // dh^-0.5
    if (t < 64) {
        float m  = (g_psum[4 * t] + g_psum[4 * t + 1] + g_psum[4 * t + 2] + g_psum[4 * t + 3]) * invN;
        float va = (g_psumsq[4 * t] + g_psumsq[4 * t + 1] + g_psumsq[4 * t + 2] + g_psumsq[4 * t + 3]) * invN - m * m;
        float sc = rsqrtf(va + 1e-5f);
        skv[t] = sc; okv[t] = -m * sc;
        m  = (g_psum[256 + 4 * t] + g_psum[257 + 4 * t] + g_psum[258 + 4 * t] + g_psum[259 + 4 * t]) * invN;
        va = (g_psumsq[256 + 4 * t] + g_psumsq[257 + 4 * t] + g_psumsq[258 + 4 * t] + g_psumsq[259 + 4 * t]) * invN - m * m;
        sc = rsqrtf(va + 1e-5f);
        sq_[t] = sc; oq_[t] = -m * sc;
    }
    __syncthreads();
    if (t < 64) {
        float aq = 0.f, ak = 0.f, av = 0.f;
        for (int c = 0; c < 64; c++) {
            aq += oq_[c] * Wq[c * 64 + t];
            ak += okv[c] * Wk[c * 64 + t];
            av += okv[c] * Wv[c * 64 + t];
        }
        g_bf4[0][t] = scale * (bq[t] + aq);
        g_bf4[1][t] = bk[t] + ak;
        g_bf4[2][t] = bv[t] + av;
        g_bf4[3][t] = bo[t];
    }
    __syncthreads();

    // pack weights: rows n (output), cols k' = [Whi | Whi | Wlo], swizzled;
    // built in smem, then copied out linearly.
    for (int p = 0; p < 4; p++) {
        const float* W = (p == 0) ? Wq : (p == 1) ? Wk : (p == 2) ? Wv : Wo;
        for (int idx = t; idx < 4096; idx += 256) {
            int c = idx >> 6, n = idx & 63;     // c = input channel (k), n = output
            float w = W[c * 64 + n];
            if (p == 0)      w *= sq_[c] * scale;
            else if (p < 3)  w *= skv[c];
            __nv_bfloat16 h = __float2bfloat16(w);
            float r = w - __bfloat162float(h);
            unsigned short hu = __bfloat16_as_ushort(h);
            unsigned short lu = __bfloat16_as_ushort(__float2bfloat16(r));
            *(unsigned short*)(spack + swz(n * 384u + (unsigned)c * 2u))         = hu;
            *(unsigned short*)(spack + swz(n * 384u + (unsigned)(64 + c) * 2u))  = hu;
            *(unsigned short*)(spack + swz(n * 384u + (unsigned)(128 + c) * 2u)) = lu;
        }
        __syncthreads();
        uint4* dst = g_Wbf + p * 1536;
        const uint4* src = (const uint4*)spack;
        for (int i = t; i < 1536; i += 256) dst[i] = src[i];
        __syncthreads();
    }
}

// ---------------- 4) warp-MMA projection ------------------------------------
// 256 threads = 8 warps; tile M=128 voxels, N=64 outputs, K'=192 (bf16 split
// [hi|lo|hi] x [Whi|Whi|Wlo]).  Each warp: one 16-voxel m-tile, 8 n-tiles,
// 12 k-tiles of mma.sync.m16n8k16.bf16.
// SEL: 0=q(skip->f_q head-major) 1=kv(f_xu->f_k,f_v head-major)
//      2=o(f_o head-major -> outext channel-first via smem bounce).
template <int NPROJ, int SEL>
__global__ __launch_bounds__(256) void proj_mma(const float* __restrict__ skip,
                                                float* __restrict__ outext) {
    extern __shared__ char smem[];          // [0,49152): A  [49152,+NPROJ*24576): B, then bias
    float* sBias = (float*)(smem + 49152 + NPROJ * 24576);

    const int tid = threadIdx.x;
    const int l = tid & 31, w = tid >> 5;
    const int vb = blockIdx.x * 128;
    const int wsel = (SEL == 0) ? 0 : (SEL == 1) ? 1 : 3;
    const float* in = (SEL == 0) ? skip : (SEL == 1) ? f_xu : f_o;

    // stage B (linear copy of pre-swizzled image)
    {
        const uint4* src = g_Wbf + wsel * 1536;
        uint4* dst = (uint4*)(smem + 49152);
        for (int i = tid; i < NPROJ * 1536; i += 256) dst[i] = src[i];
    }
    if (tid < NPROJ * 64) sBias[tid] = g_bf4[wsel + (tid >> 6)][tid & 63];

    // stage A: each thread = one voxel row half (32 channels)
    {
        int vox = tid & 127;
        int hh = tid >> 7;
        float xv[32];
        if (SEL != 2) {
#pragma unroll
            for (int j = 0; j < 32; j++)
                xv[j] = in[(size_t)(hh * 32 + j) * NVOX + vb + vox];
        } else {
            // head-major input: channel c = head*8+d at in[head*NVOX*8 + v*8 + d]
#pragma unroll
            for (int g = 0; g < 4; g++) {
                int head = hh * 4 + g;
                const float4* pa = (const float4*)(in + (size_t)head * NVOX * 8
                                                   + (size_t)(vb + vox) * 8);
                float4 a = pa[0], b = pa[1];
                xv[g * 8 + 0] = a.x; xv[g * 8 + 1] = a.y; xv[g * 8 + 2] = a.z; xv[g * 8 + 3] = a.w;
                xv[g * 8 + 4] = b.x; xv[g * 8 + 5] = b.y; xv[g * 8 + 6] = b.z; xv[g * 8 + 7] = b.w;
            }
        }
        unsigned rowb = (unsigned)vox * 384u;
#pragma unroll
        for (int g = 0; g < 4; g++) {
            unsigned hp[4], lp[4];
#pragma unroll
            for (int e = 0; e < 4; e++) {
                float a = xv[g * 8 + 2 * e], b = xv[g * 8 + 2 * e + 1];
                __nv_bfloat16 ha = __float2bfloat16(a), hb = __float2bfloat16(b);
                float ra = a - __bfloat162float(ha);
                float rb = b - __bfloat162float(hb);
                hp[e] = ((unsigned)__bfloat16_as_ushort(hb) << 16) | __bfloat16_as_ushort(ha);
                lp[e] = ((unsigned)__bfloat16_as_ushort(__float2bfloat16(rb)) << 16)
                      | (unsigned)__bfloat16_as_ushort(__float2bfloat16(ra));
            }
            unsigned cb = (unsigned)((tid >> 7) * 64 + g * 16);
            *(uint4*)(smem + swz(rowb + cb))        = make_uint4(hp[0], hp[1], hp[2], hp[3]);
            *(uint4*)(smem + swz(rowb + 128u + cb)) = make_uint4(lp[0], lp[1], lp[2], lp[3]);
            *(uint4*)(smem + swz(rowb + 256u + cb)) = make_uint4(hp[0], hp[1], hp[2], hp[3]);
        }
    }
    __syncthreads();

    const unsigned sAu = smem_u32(smem);
    const unsigned sBu = sAu + 49152;
    const int m0 = w * 16;
    const unsigned arow = (unsigned)(m0 + (l & 7) + ((l >> 3) & 1) * 8);
    const unsigned acolb = (unsigned)((l >> 4) * 16);          // bytes
    const unsigned brow = (unsigned)((l & 7) + ((l >> 4) & 1) * 8);
    const unsigned bcolb = (unsigned)(((l >> 3) & 1) * 16);    // bytes

    float acc[NPROJ][8][4];
#pragma unroll
    for (int p = 0; p < NPROJ; p++)
#pragma unroll
        for (int nt = 0; nt < 8; nt++)
#pragma unroll
            for (int e = 0; e < 4; e++) acc[p][nt][e] = 0.f;

#pragma unroll
    for (int kt = 0; kt < 12; kt++) {
        unsigned kb = (unsigned)kt * 32u;     // 16 elements * 2B
        unsigned a0, a1, a2, a3;
        LDSM4(a0, a1, a2, a3, sAu + swz(arow * 384u + kb + acolb));
#pragma unroll
        for (int ntp = 0; ntp < 4; ntp++) {
#pragma unroll
            for (int p = 0; p < NPROJ; p++) {
                unsigned b0, b1, b2, b3;
                unsigned baddr = sBu + (unsigned)p * 24576u
                               + swz(((unsigned)(ntp * 16) + brow) * 384u + kb + bcolb);
                LDSM4(b0, b1, b2, b3, baddr);
                MMA16816(acc[p][2 * ntp],     a0, a1, a2, a3, b0, b1);
                MMA16816(acc[p][2 * ntp + 1], a0, a1, a2, a3, b2, b3);
            }
        }
    }

    const int gid = l >> 2, tig = l & 3;
    if (SEL != 2) {
        // head-major store: out[head][vox][8]; n-tile nt == head, d = tig*2
#pragma unroll
        for (int p = 0; p < NPROJ; p++) {
            float* out = (SEL == 0) ? f_q : (p == 0 ? f_k : f_v);
#pragma unroll
            for (int nt = 0; nt < 8; nt++) {
                size_t hb = (size_t)nt * NVOX * 8;
                int ch = nt * 8 + tig * 2;
                float2 v0, v1;
                v0.x = acc[p][nt][0] + sBias[p * 64 + ch];
                v0.y = acc[p][nt][1] + sBias[p * 64 + ch + 1];
                v1.x = acc[p][nt][2] + sBias[p * 64 + ch];
                v1.y = acc[p][nt][3] + sBias[p * 64 + ch + 1];
                *(float2*)(out + hb + (size_t)(vb + m0 + gid) * 8 + tig * 2)     = v0;
                *(float2*)(out + hb + (size_t)(vb + m0 + gid + 8) * 8 + tig * 2) = v1;
            }
        }
    } else {
        // channel-first bounce: sOut[64][132] (pad -> conflict-free)
        __syncthreads();
        float* sOut = (float*)smem;
#pragma unroll
        for (int nt = 0; nt < 8; nt++) {
            int ch = nt * 8 + tig * 2;
            int v0 = m0 + gid, v1 = v0 + 8;
            sOut[ch * 132 + v0]       = acc[0][nt][0] + sBias[ch];
            sOut[(ch + 1) * 132 + v0] = acc[0][nt][1] + sBias[ch + 1];
            sOut[ch * 132 + v1]       = acc[0][nt][2] + sBias[ch];
            sOut[(ch + 1) * 132 + v1] = acc[0][nt][3] + sBias[ch + 1];
        }
        __syncthreads();
        for (int i = tid; i < 64 * 32; i += 256) {
            int ch = i >> 5, vv = (i & 31) * 4;
            float4 o4;
            o4.x = sOut[ch * 132 + vv];
            o4.y = sOut[ch * 132 + vv + 1];
            o4.z = sOut[ch * 132 + vv + 2];
            o4.w = sOut[ch * 132 + vv + 3];
            *(float4*)(outext + (size_t)ch * NVOX + vb + vv) = o4;
        }
    }
}

// ---------------- 5) tiled neighborhood attention (head-major, f32x2) -------
__device__ __forceinline__ int sidx(int hl, int j) {
    return (hl * 2 + j) ^ (((hl >> 2) & 3) << 1);
}

__global__ __launch_bounds__(256) void attn_kernel(const float* __restrict__ rpb) {
    __shared__ float4 ks4[1216];
    __shared__ float4 vs4[1216];
    __shared__ float bias_s[125];

    int tid  = threadIdx.x;
    int tb   = blockIdx.x;          // 0..255 : 8x8x4 tiles
    int head = blockIdx.y;
    int h0 = (tb >> 5) * 8;
    int w0 = ((tb >> 2) & 7) * 8;
    int z0 = (tb & 3) * 4;

    const float* kh = f_k + (size_t)head * NVOX * 8;
    const float* vh = f_v + (size_t)head * NVOX * 8;

    for (int i = tid; i < 600; i += 256) {
        int ah = i / 60; int r = i - ah * 60; int aw = r / 6; int az = r - aw * 6;
        int gh = min(max(h0 - 1 + ah, 0), 63);
        int gw = min(max(w0 - 1 + aw, 0), 63);
        int gz = min(max(z0 - 1 + az, 0), 15);
        int gv = ((gh << 6) + gw) * 16 + gz;
        const float4* pk = (const float4*)(kh + (size_t)gv * 8);
        ks4[sidx(i, 0)] = pk[0];
        ks4[sidx(i, 1)] = pk[1];
        const float4* pv = (const float4*)(vh + (size_t)gv * 8);
        vs4[sidx(i, 0)] = pv[0];
        vs4[sidx(i, 1)] = pv[1];
    }
    if (tid < 125) bias_s[tid] = rpb[head * 125 + tid];
    __syncthreads();

    int lth = tid >> 5;
    int ltw = (tid >> 2) & 7;
    int ltz = tid & 3;
    int h = h0 + lth, w = w0 + ltw, z = z0 + ltz;
    int v = ((h << 6) + w) * 16 + z;

    const ulonglong2* pq = (const ulonglong2*)(f_q + (size_t)head * NVOX * 8 + (size_t)v * 8);
    ulonglong2 qa = pq[0], qb = pq[1];

    int sh = min(max(h - 1, 0), 61);
    int sw = min(max(w - 1, 0), 61);
    int sz = min(max(z - 1, 0), 13);
    int lhh = sh - h0 + 1, lww = sw - w0 + 1, lzz = sz - z0 + 1;
    int rb = (sh - h + 2) * 25 + (sw - w + 2) * 5 + (sz - z + 2);

    float logits[27];
    int   hls[27];
    float mx = -1e30f;
#pragma unroll
    for (int a = 0; a < 3; a++)
#pragma unroll
    for (int b = 0; b < 3; b++)
#pragma unroll
    for (int cc = 0; cc < 3; cc++) {
        int m  = (a * 3 + b) * 3 + cc;
        int hl = ((lhh + a) * 10 + (lww + b)) * 6 + (lzz + cc);
        hls[m] = hl;
        ulonglong2 ka = *(const ulonglong2*)&ks4[sidx(hl, 0)];
        ulonglong2 kb = *(const ulonglong2*)&ks4[sidx(hl, 1)];
        u64 d2 = fmul2(qa.x, ka.x);
        d2 = ffma2(qa.y, ka.y, d2);
        d2 = ffma2(qb.x, kb.x, d2);
        d2 = ffma2(qb.y, kb.y, d2);
        float d = f2lo(d2) + f2hi(d2) + bias_s[rb + a * 25 + b * 5 + cc];
        logits[m] = d;
        mx = fmaxf(mx, d);
    }
    float ssum = 0.f;
#pragma unroll
    for (int m = 0; m < 27; m++) {
        float e = __expf(logits[m] - mx);
        logits[m] = e;
        ssum += e;
    }
    float inv = 1.0f / ssum;
    u64 o01 = 0, o23 = 0, o45 = 0, o67 = 0;
#pragma unroll
    for (int m = 0; m < 27; m++) {
        u64 a2 = packdup(logits[m] * inv);
        ulonglong2 va = *(const ulonglong2*)&vs4[sidx(hls[m], 0)];
        ulonglong2 vb = *(const ulonglong2*)&vs4[sidx(hls[m], 1)];
        o01 = ffma2(a2, va.x, o01);
        o23 = ffma2(a2, va.y, o23);
        o45 = ffma2(a2, vb.x, o45);
        o67 = ffma2(a2, vb.y, o67);
    }
    // head-major contiguous 32B store
    float* oh = f_o + (size_t)head * NVOX * 8 + (size_t)v * 8;
    ulonglong2 s0; s0.x = o01; s0.y = o23;
    ulonglong2 s1; s1.x = o45; s1.y = o67;
    *(ulonglong2*)(oh)     = s0;
    *(ulonglong2*)(oh + 4) = s1;
}

// ---------------------------------------------------------------------------
extern "C" void kernel_launch(void* const* d_in, const int* in_sizes, int n_in,
                              void* d_out, int out_size) {
    const float* x    = (const float*)d_in[0];
    const float* skip = (const float*)d_in[1];
    const float* Wq   = (const float*)d_in[2];
    const float* bq   = (const float*)d_in[3];
    const float* Wk   = (const float*)d_in[4];
    const float* bk   = (const float*)d_in[5];
    const float* Wv   = (const float*)d_in[6];
    const float* bv   = (const float*)d_in[7];
    const float* Wo   = (const float*)d_in[8];
    const float* bo   = (const float*)d_in[9];
    const float* rpb  = (const float*)d_in[10];
    float* out = (float*)d_out;

    const int SMEM1 = 49152 + 24576 + 512;       // 74240
    const int SMEM2 = 49152 + 2 * 24576 + 512;   // 98816
    cudaFuncSetAttribute(proj_mma<1, 0>, cudaFuncAttributeMaxDynamicSharedMemorySize, SMEM1);
    cudaFuncSetAttribute(proj_mma<2, 1>, cudaFuncAttributeMaxDynamicSharedMemorySize, SMEM2);
    cudaFuncSetAttribute(proj_mma<1, 2>, cudaFuncAttributeMaxDynamicSharedMemorySize, SMEM1);

    upsample_kernel<<<dim3(256, 8), 256>>>(x);
    stats_kernel<<<512, 256>>>(skip);
    fold_kernel<<<1, 256>>>(Wq, bq, Wk, bk, Wv, bv, Wo, bo);
    proj_mma<1, 0><<<512, 256, SMEM1>>>(skip, nullptr);   // q
    proj_mma<2, 1><<<512, 256, SMEM2>>>(skip, nullptr);   // k + v
    attn_kernel<<<dim3(256, 8), 256>>>(rpb);
    proj_mma<1, 2><<<512, 256, SMEM1>>>(skip, out);       // o
}